// round 4
// baseline (speedup 1.0000x reference)
#include <cuda_runtime.h>
#include <math.h>

// ----------------------------------------------------------------------------
// UnifiedKAN: 2-layer KAN with learned-knot cubic B-splines.
// Splines = piecewise cubics over 6 real intervals. Setup (20 blocks, fp32,
// one reciprocal per interval) -> per-interval records {c0,c1,c2,c3,m}.
// Main kernel: 5-compare predicated-add interval search + fused record fetch
// (LDS.128 + LDS) + centered Horner; branchless layer-2 masking.
// ----------------------------------------------------------------------------

#define GRID_ 5
#define IN_ 4
#define HID_ 4
#define NSPL 20
// Per-spline record (64 floats, 256B):
// [0..3] interior knots 0..3, [4] knot 4, [5..7] pad,
// [8 + 8*j .. ] interval j: {c0,c1,c2,c3,m,pad,pad,pad}
#define SPL_STRIDE 64
#define PARAMS_W 1280  // softmax weights (8 floats)
#define PARAMS_B 1288  // base offset scalar
#define PARAMS_N 1289

__device__ float g_params[1312];

// Reference float32 Cox-de Boor (truncated to first 8 basis fns), denominators
// replaced by precomputed reciprocals rc[] (0 when den<=1e-8).
__device__ __forceinline__ float eval_ref_spline(float x, const float* kn /*13*/,
                                                 const float* rc /*33*/,
                                                 const float* cf /*8*/) {
    float b[12];
    #pragma unroll
    for (int j = 0; j < 12; j++)
        b[j] = (x >= kn[j] && x < kn[j + 1]) ? 1.0f : 0.0f;
    if (x == kn[12]) b[11] += 1.0f;
    const int off[4] = {0, 0, 12, 23};
    #pragma unroll
    for (int d = 1; d <= 3; d++) {
        int n = 12 - d;
        const float* r = rc + off[d];
        #pragma unroll
        for (int j = 0; j < 11; j++) {
            if (j >= n) break;
            float t1 = (x - kn[j]) * r[j] * b[j];
            float t2 = (kn[d + 1 + j] - x) * r[j + 1] * b[j + 1];
            b[j] = t1 + t2;  // in-place ascending: b[j+1] still old value
        }
    }
    float s = 0.0f;
    #pragma unroll
    for (int j = 0; j < 8; j++) s += b[j] * cf[j];
    return s;
}

// One block per spline, 32 threads.
__global__ void kan_setup_kernel(const float* __restrict__ l1_coeffs,
                                 const float* __restrict__ l1_kd,
                                 const float* __restrict__ op_alpha,
                                 const float* __restrict__ gumbel,
                                 const float* __restrict__ l2_coeffs,
                                 const float* __restrict__ l2_kd,
                                 const float* __restrict__ base_offset) {
    __shared__ float s_rc[33];
    __shared__ float s_fv[24];   // [6 intervals][4 nodes]

    int s = blockIdx.x;
    int lane = threadIdx.x;
    const float* kd = (s < 16) ? (l1_kd + s * (GRID_ + 1)) : (l2_kd + (s - 16) * (GRID_ + 1));
    const float* cf = (s < 16) ? (l1_coeffs + s * 8) : (l2_coeffs + (s - 16) * 8);

    // Every lane redundantly computes the 13-knot vector (lockstep, cheap).
    float d[GRID_ + 1];
    float dsum = 0.0f;
    #pragma unroll
    for (int k = 0; k < GRID_ + 1; k++) {
        float v = kd[k];
        d[k] = fmaxf(v, 0.0f) + log1pf(expf(-fabsf(v)));  // stable softplus
        dsum += d[k];
    }
    float kn[13];
    kn[0] = kn[1] = kn[2] = kn[3] = -1.0f;
    float cum = 0.0f;
    #pragma unroll
    for (int k = 0; k < 5; k++) {
        cum += d[k] / dsum * 2.0f;
        kn[4 + k] = -1.0f + cum;
    }
    kn[9] = kn[10] = kn[11] = kn[12] = 1.0f;

    // Reciprocals of the 33 knot-difference denominators (masked to 0).
    for (int t = lane; t < 33; t += 32) {
        int dd, j;
        if (t < 12)      { dd = 1; j = t; }
        else if (t < 23) { dd = 2; j = t - 12; }
        else             { dd = 3; j = t - 23; }
        float den = kn[dd + j] - kn[j];
        s_rc[t] = (den > 1e-8f) ? 1.0f / den : 0.0f;
    }
    __syncthreads();

    // Lanes 0..23: each samples ONE node of ONE interval.
    if (lane < 24) {
        int j = lane >> 2, k = lane & 3;
        float lo = kn[3 + j], hi = kn[4 + j];
        float u = lo + (hi - lo) * (0.125f + 0.25f * (float)k);
        s_fv[lane] = eval_ref_spline(u, kn, s_rc, cf);
    } else if (s == 0) {
        int h = lane - 24;
        if (h < HID_) {
            float a0 = op_alpha[h * 2 + 0] + gumbel[h * 2 + 0];
            float a1 = op_alpha[h * 2 + 1] + gumbel[h * 2 + 1];
            float mx = fmaxf(a0, a1);
            float e0 = expf(a0 - mx), e1 = expf(a1 - mx);
            float inv = 1.0f / (e0 + e1);
            g_params[PARAMS_W + h * 2 + 0] = e0 * inv;
            g_params[PARAMS_W + h * 2 + 1] = e1 * inv;
        }
        if (lane == 28) g_params[PARAMS_B] = base_offset[0];
    }
    __syncthreads();

    float* P = g_params + s * SPL_STRIDE;
    if (lane < 5) P[lane] = kn[4 + lane];  // interior knots

    // Lanes 0..5: fit exact cubic on interval j via fp32 divided differences.
    // Nodes equispaced in s=(x-m)/w at {-3/8,-1/8,1/8,3/8}; one reciprocal rw.
    if (lane < 6) {
        int j = lane;
        float lo = kn[3 + j], hi = kn[4 + j];
        float w = hi - lo;
        float m = lo + 0.5f * w;
        float rw = 1.0f / w;
        float f0 = s_fv[j * 4 + 0], f1 = s_fv[j * 4 + 1];
        float f2 = s_fv[j * 4 + 2], f3 = s_fv[j * 4 + 3];
        float d1a = 4.0f * (f1 - f0);
        float d1b = 4.0f * (f2 - f1);
        float d1c = 4.0f * (f3 - f2);
        float d2a = 2.0f * (d1b - d1a);
        float d2b = 2.0f * (d1c - d1b);
        float d3  = (4.0f / 3.0f) * (d2b - d2a);
        // Expand Newton form to monomial in s (nodes -3/8,-1/8,1/8):
        float p0 = d3, p1 = 0.0f, p2 = 0.0f, p3 = 0.0f;
        const float nodes[3] = {0.125f, -0.125f, -0.375f};
        const float adds[3]  = {d2a, d1a, f0};
        #pragma unroll
        for (int st = 0; st < 3; st++) {
            float vv = nodes[st];
            float q3 = p2, q2 = p1, q1 = p0;
            float q0 = adds[st] - vv * p0;
            q1 -= vv * p1; q2 -= vv * p2; q3 -= vv * p3;
            p0 = q0; p1 = q1; p2 = q2; p3 = q3;
        }
        float rw2 = rw * rw;
        float* R = P + 8 + 8 * j;
        R[0] = p0;
        R[1] = p1 * rw;
        R[2] = p2 * rw2;
        R[3] = p3 * rw2 * rw;
        R[4] = m;
    }
}

__device__ __forceinline__ float eval_spline_sh(float x, const float* sp) {
    float4 kv = *reinterpret_cast<const float4*>(sp);   // broadcast LDS.128
    float k4 = sp[4];
    int off = ((x >= kv.x) + (x >= kv.y) + (x >= kv.z) + (x >= kv.w) + (x >= k4)) << 3;
    const float* rec = sp + 8 + off;
    float4 c = *reinterpret_cast<const float4*>(rec);   // divergent LDS.128
    float m = rec[4];                                   // divergent LDS.32
    float t = x - m;
    return fmaf(fmaf(fmaf(c.w, t, c.z), t, c.y), t, c.x);
}

__global__ void __launch_bounds__(256) kan_main_kernel(const float4* __restrict__ x,
                                                       float* __restrict__ out, int n) {
    __shared__ __align__(16) float sp[1312];
    for (int k = threadIdx.x; k < PARAMS_N; k += blockDim.x) sp[k] = g_params[k];
    __syncthreads();

    int i0 = blockIdx.x * blockDim.x + threadIdx.x;
    if (i0 >= n) return;

    float4 xv = x[i0];
    float xi[4] = {xv.x, xv.y, xv.z, xv.w};

    float acc = sp[PARAMS_B];
    #pragma unroll
    for (int h = 0; h < HID_; h++) {
        float sum = 0.0f, prod = 1.0f;
        #pragma unroll
        for (int i = 0; i < IN_; i++) {
            float v = eval_spline_sh(xi[i], sp + (h * IN_ + i) * SPL_STRIDE);
            sum += v;
            prod *= fminf(fmaxf(v, -5.0f), 5.0f);
        }
        float hid = sp[PARAMS_W + h * 2 + 0] * sum + sp[PARAMS_W + h * 2 + 1] * prod;
        // Branchless: clamped compares give valid idx (0 or 5) out of range;
        // mask the result instead of branching.
        float v2 = eval_spline_sh(hid, sp + (16 + h) * SPL_STRIDE);
        bool in_range = (hid >= -1.0f) && (hid <= 1.0f);
        acc += in_range ? v2 : 0.0f;
    }
    out[i0] = acc;
}

extern "C" void kernel_launch(void* const* d_in, const int* in_sizes, int n_in,
                              void* d_out, int out_size) {
    const float* x          = (const float*)d_in[0];
    const float* l1_coeffs  = (const float*)d_in[1];
    const float* l1_kd      = (const float*)d_in[2];
    const float* op_alpha   = (const float*)d_in[3];
    const float* gumbel     = (const float*)d_in[4];
    const float* l2_coeffs  = (const float*)d_in[5];
    const float* l2_kd      = (const float*)d_in[6];
    const float* base_off   = (const float*)d_in[7];
    float* out = (float*)d_out;

    int n = in_sizes[0] / IN_;  // N samples

    kan_setup_kernel<<<NSPL, 32>>>(l1_coeffs, l1_kd, op_alpha, gumbel,
                                   l2_coeffs, l2_kd, base_off);
    int threads = 256;
    int blocks = (n + threads - 1) / threads;
    kan_main_kernel<<<blocks, threads>>>((const float4*)x, out, n);
}